// round 16
// baseline (speedup 1.0000x reference)
// ============================================================================
// R16 submission.
//
// Post-mortem R15: merged-dwf WIN (813 -> 810.2; dwf now a single 246us
// launch, occ 72.2, dram 18.6). Small but real; keep.
//
// Remaining budget: pw ~475us (floor from fma2 rate: ~268us), dwf 246us,
// tail ~90us. Largest single pw = kv-c1 (128x128, ~190us vs ~122us fma2
// floor). Its blocks are RF+smem bound at 2/SM, so the 64KB staging phase is
// poorly hidden.
//
// R16 change: split kv-c1 along COUT (not PIX — R14 proved PIX-splitting
// loses by doubling weight traffic). New dedicated kernel pw_split:
//   grid (512, 4, 2); z selects oc-half [0,64) / [64,128). Each block stages
//   the SAME full 128x128 input tile (smem 64KB) but computes only 64
//   outputs: JM=4 -> acc regs halve (~75 total), __launch_bounds__(256,3)
//   -> 3 blocks/SM (smem 227/64 = 3). Weight traffic per block halves
//   (only its 64 rows), so unlike R14 total weight LDG is UNCHANGED; only
//   input staging doubles (+128MB reads, DRAM at 14% has headroom).
//   +50% resident warps -> staging of one block overlaps compute of two.
//   GN stats group = z (block-uniform), bit-identical accumulation order
//   within each group half vs before.
// Everything else R15-exact.
//
// Prediction: kv-c1 190 -> ~150us => total 810 -> ~775us, rel_err ~6.6e-7.
// If neutral/regressed, COUT-split closes and next round goes tf32-MMA.
// ============================================================================
#include <cuda_runtime.h>
#include <cstdint>
#include <cstddef>
#include <math.h>

#define HW   65536
#define HH   256
#define WWD  256
#define BB   4

// ---------------- scratch (static device globals; no allocation) ----------------
__device__ float  g_kv0[(size_t)BB * 128 * HW];
__device__ float  g_kv1[(size_t)BB * 128 * HW];
__device__ float  g_q0 [(size_t)BB * 64  * HW];
__device__ float  g_q1 [(size_t)BB * 64  * HW];
__device__ double g_sum_kv[BB * 4];
__device__ double g_sum_q [BB * 4];
__device__ float  g_aff_kv[BB * 128 * 2];
__device__ float  g_aff_q [BB * 64  * 2];
__device__ float  g_G  [BB * 4 * 256];
__device__ float  g_qss[BB * 4 * 16];
__device__ float  g_kss[BB * 4 * 16];
__device__ float  g_M  [BB * 64 * 64];

// ---------------- helpers ----------------
__device__ __forceinline__ unsigned long long pk2(float a, float b) {
    unsigned long long r;
    asm("mov.b64 %0, {%1,%2};" : "=l"(r) : "f"(a), "f"(b));
    return r;
}
__device__ __forceinline__ unsigned long long fma2(unsigned long long a, unsigned long long b,
                                                   unsigned long long c) {
    unsigned long long d;
    asm("fma.rn.f32x2 %0, %1, %2, %3;" : "=l"(d) : "l"(a), "l"(b), "l"(c));
    return d;
}
__device__ __forceinline__ float2 up2(unsigned long long v) {
    float2 r;
    asm("mov.b64 {%0,%1}, %2;" : "=f"(r.x), "=f"(r.y) : "l"(v));
    return r;
}
__device__ __forceinline__ float lrelu(float x) { return x > 0.f ? x : 0.2f * x; }

// ---------------- zero small reduction buffers ----------------
__global__ void zero_kernel() {
    int t = threadIdx.x;
    if (t < 16) { g_sum_kv[t] = 0.0; g_sum_q[t] = 0.0; }
    for (int i = t; i < 4096; i += 256) g_G[i] = 0.f;
    g_qss[t] = 0.f; g_kss[t] = 0.f;
}

// ---------------- pointwise 1x1 conv (tall GEMM), packed f32x2 (R10-exact) ------
template <int CIN, int COUT, int PIX, bool BIAS, bool STATS, bool VAFF>
__global__ void __launch_bounds__(256) pw_kernel(
    const float* __restrict__ in, size_t inBStride,
    const float* __restrict__ w, size_t wBStride,
    const float* __restrict__ bias,
    const float* __restrict__ aff, int affCOff, int affCStride,
    float* __restrict__ out, double* __restrict__ stats)
{
    extern __shared__ float sm[];          // CIN * PIX floats
    __shared__ float red[256][4];
    const int tid = threadIdx.x;
    const int b = blockIdx.y;
    const int pix0 = blockIdx.x * PIX;
    const float* ib = in + (size_t)b * inBStride + pix0;
    const float* wb = w + (size_t)b * wBStride;

    constexpr int P4 = PIX / 4;
#pragma unroll
    for (int l = 0; l < CIN * PIX / 1024; l++) {
        int idx = tid + l * 256;
        int c = idx / P4, p4 = idx % P4;
        float4 v = *(const float4*)(ib + (size_t)c * HW + p4 * 4);
        if (VAFF) {
            const float* ap = aff + ((size_t)b * affCStride + affCOff + c) * 2;
            float aa = ap[0], bc = ap[1];
            v.x = lrelu(fmaf(aa, v.x, bc));
            v.y = lrelu(fmaf(aa, v.y, bc));
            v.z = lrelu(fmaf(aa, v.z, bc));
            v.w = lrelu(fmaf(aa, v.w, bc));
        }
        *(float4*)(sm + c * PIX + p4 * 4) = v;
    }
    __syncthreads();

    constexpr int JM = COUT / 16;
    constexpr int NI = PIX / 32;
    unsigned long long acc[JM][NI];
#pragma unroll
    for (int j = 0; j < JM; j++)
#pragma unroll
        for (int i = 0; i < NI; i++) acc[j][i] = 0ull;

    const int r = tid >> 4, cp = tid & 15;
    const unsigned long long* s2 = (const unsigned long long*)sm;

    for (int k0 = 0; k0 < CIN; k0 += 4) {
        float4 wq[JM];
#pragma unroll
        for (int j = 0; j < JM; j++)
            wq[j] = *(const float4*)(wb + (r + 16 * j) * CIN + k0);
#pragma unroll
        for (int kk = 0; kk < 4; kk++) {
            int k = k0 + kk;
            unsigned long long xv[NI];
#pragma unroll
            for (int i = 0; i < NI; i++) xv[i] = s2[k * (PIX / 2) + cp + 16 * i];
#pragma unroll
            for (int j = 0; j < JM; j++) {
                float wv = ((const float*)&wq[j])[kk];
                unsigned long long wp = pk2(wv, wv);
#pragma unroll
                for (int i = 0; i < NI; i++) acc[j][i] = fma2(xv[i], wp, acc[j][i]);
            }
        }
    }

    float sumg[2] = {0.f, 0.f}, ssqg[2] = {0.f, 0.f};
#pragma unroll
    for (int j = 0; j < JM; j++) {
        int oc = r + 16 * j;
        float bs = BIAS ? bias[oc] : 0.f;
        float* op = out + ((size_t)b * COUT + oc) * HW + pix0;
#pragma unroll
        for (int i = 0; i < NI; i++) {
            float2 v = up2(acc[j][i]);
            v.x += bs; v.y += bs;
            *(float2*)(op + 2 * (cp + 16 * i)) = v;
            if (STATS) {
                int g = (j >= JM / 2) ? 1 : 0;
                sumg[g] += v.x + v.y;
                ssqg[g] += v.x * v.x + v.y * v.y;
            }
        }
    }

    if (STATS) {
        red[tid][0] = sumg[0]; red[tid][1] = ssqg[0];
        red[tid][2] = sumg[1]; red[tid][3] = ssqg[1];
        __syncthreads();
        for (int s = 128; s > 0; s >>= 1) {
            if (tid < s) {
#pragma unroll
                for (int m = 0; m < 4; m++) red[tid][m] += red[tid + s][m];
            }
            __syncthreads();
        }
        if (tid == 0) {
            atomicAdd(&stats[b * 4 + 0], (double)red[0][0]);
            atomicAdd(&stats[b * 4 + 1], (double)red[0][1]);
            atomicAdd(&stats[b * 4 + 2], (double)red[0][2]);
            atomicAdd(&stats[b * 4 + 3], (double)red[0][3]);
        }
    }
}

// ---------------- kv-c1 COUT-split kernel: CIN=128, 64 outputs/block ------------
// grid (512, 4, 2); blockIdx.z = oc half. Stats group = half.
__global__ void __launch_bounds__(256, 3) pw_split(
    const float* __restrict__ in,
    const float* __restrict__ w,
    const float* __restrict__ bias,
    float* __restrict__ out, double* __restrict__ stats)
{
    constexpr int CIN = 128, PIX = 128, JM = 4, NI = 4;
    extern __shared__ float sm[];          // 64KB
    __shared__ float red[256][2];
    const int tid = threadIdx.x;
    const int b = blockIdx.y;
    const int half = blockIdx.z;
    const int ocOff = 64 * half;
    const int pix0 = blockIdx.x * PIX;
    const float* ib = in + (size_t)b * (size_t)128 * HW + pix0;

    constexpr int P4 = PIX / 4;
#pragma unroll
    for (int l = 0; l < CIN * PIX / 1024; l++) {
        int idx = tid + l * 256;
        int c = idx / P4, p4 = idx % P4;
        float4 v = *(const float4*)(ib + (size_t)c * HW + p4 * 4);
        *(float4*)(sm + c * PIX + p4 * 4) = v;
    }
    __syncthreads();

    unsigned long long acc[JM][NI];
#pragma unroll
    for (int j = 0; j < JM; j++)
#pragma unroll
        for (int i = 0; i < NI; i++) acc[j][i] = 0ull;

    const int r = tid >> 4, cp = tid & 15;
    const unsigned long long* s2 = (const unsigned long long*)sm;

    for (int k0 = 0; k0 < CIN; k0 += 4) {
        float4 wq[JM];
#pragma unroll
        for (int j = 0; j < JM; j++)
            wq[j] = *(const float4*)(w + (ocOff + r + 16 * j) * CIN + k0);
#pragma unroll
        for (int kk = 0; kk < 4; kk++) {
            int k = k0 + kk;
            unsigned long long xv[NI];
#pragma unroll
            for (int i = 0; i < NI; i++) xv[i] = s2[k * (PIX / 2) + cp + 16 * i];
#pragma unroll
            for (int j = 0; j < JM; j++) {
                float wv = ((const float*)&wq[j])[kk];
                unsigned long long wp = pk2(wv, wv);
#pragma unroll
                for (int i = 0; i < NI; i++) acc[j][i] = fma2(xv[i], wp, acc[j][i]);
            }
        }
    }

    float sumg = 0.f, ssqg = 0.f;
#pragma unroll
    for (int j = 0; j < JM; j++) {
        int oc = ocOff + r + 16 * j;
        float bs = bias[oc];
        float* op = out + ((size_t)b * 128 + oc) * HW + pix0;
#pragma unroll
        for (int i = 0; i < NI; i++) {
            float2 v = up2(acc[j][i]);
            v.x += bs; v.y += bs;
            *(float2*)(op + 2 * (cp + 16 * i)) = v;
            sumg += v.x + v.y;
            ssqg += v.x * v.x + v.y * v.y;
        }
    }

    red[tid][0] = sumg; red[tid][1] = ssqg;
    __syncthreads();
    for (int s = 128; s > 0; s >>= 1) {
        if (tid < s) {
            red[tid][0] += red[tid + s][0];
            red[tid][1] += red[tid + s][1];
        }
        __syncthreads();
    }
    if (tid == 0) {
        atomicAdd(&stats[b * 4 + half * 2 + 0], (double)red[0][0]);
        atomicAdd(&stats[b * 4 + half * 2 + 1], (double)red[0][1]);
    }
}

// ---------------- fused depthwise, MERGED q+kv launch (R15-exact) --------------
__global__ void __launch_bounds__(256, 6) dwf_kernel(
    const float* __restrict__ qin,  float* __restrict__ qout,
    const float* __restrict__ kin,  float* __restrict__ kout,
    const float* __restrict__ qw5, const float* __restrict__ qb5,
    const float* __restrict__ qw3, const float* __restrict__ qb3,
    const float* __restrict__ kw5, const float* __restrict__ kb5,
    const float* __restrict__ kw3, const float* __restrict__ kb3)
{
    __shared__ float s[44][76];
    __shared__ float m[38][72];
    __shared__ float wts[36];
    const int tid = threadIdx.x;
    const bool isq = (blockIdx.z < 256);
    const int bc = isq ? blockIdx.z : (blockIdx.z - 256);
    const int C = isq ? 64 : 128;
    const int c = bc % C;
    const float* in = (isq ? qin : kin);
    float* out = (isq ? qout : kout);
    const float* w5 = isq ? qw5 : kw5;
    const float* b5 = isq ? qb5 : kb5;
    const float* w3 = isq ? qw3 : kw3;
    const float* b3 = isq ? qb3 : kb3;
    const int x0 = blockIdx.x * 64, y0 = blockIdx.y * 32;

    if (tid < 25) wts[tid] = w5[c * 25 + tid];
    else if (tid == 25) wts[25] = b5[c];
    else if (tid < 35) wts[tid] = w3[c * 9 + (tid - 26)];
    else if (tid == 35) wts[35] = b3[c];

    const float* ip = in + (size_t)bc * HW;
    for (int idx = tid; idx < 42 * 74; idx += 256) {
        int row = idx / 74, col = idx % 74;
        int gy = y0 + row - 5, gx = x0 + col - 5;
        float v = 0.f;
        if (gy >= 0 && gy < HH && gx >= 0 && gx < WWD) v = ip[gy * WWD + gx];
        s[row][col] = v;
    }
    __syncthreads();

    for (int t = tid; t < 350; t += 256) {
        int ss = t / 70, j = t % 70;
        int r0 = ss * 8;
        int nr = 38 - r0; if (nr > 8) nr = 8;
        int gx = x0 - 3 + j;
        bool xin = (gx >= 0 && gx < WWD);
        float acc[8];
#pragma unroll
        for (int i = 0; i < 8; i++) acc[i] = wts[25];
#pragma unroll
        for (int dx = 0; dx < 5; dx++) {
            float v[12];
#pragma unroll
            for (int rr = 0; rr < 12; rr++) v[rr] = s[r0 + rr][j + dx];
#pragma unroll
            for (int dy = 0; dy < 5; dy++) {
                float wv = wts[dy * 5 + dx];
#pragma unroll
                for (int i = 0; i < 8; i++) acc[i] = fmaf(v[dy + i], wv, acc[i]);
            }
        }
#pragma unroll
        for (int i = 0; i < 8; i++) {
            if (i < nr) {
                int gy = y0 - 3 + r0 + i;
                bool in_img = xin && (gy >= 0) && (gy < HH);
                m[r0 + i][j] = in_img ? acc[i] : 0.f;
            }
        }
    }
    __syncthreads();

    const int tx = tid & 63, ty = (tid >> 6) << 3;
    float bs = wts[35];
    float a[8];
#pragma unroll
    for (int i = 0; i < 8; i++) a[i] = bs;
#pragma unroll
    for (int dxi = 0; dxi < 3; dxi++) {
        int colx = tx + 3 * dxi;
        float v[14];
#pragma unroll
        for (int rr = 0; rr < 14; rr++) v[rr] = m[ty + rr][colx];
#pragma unroll
        for (int dyi = 0; dyi < 3; dyi++) {
            float wv = wts[26 + dyi * 3 + dxi];
#pragma unroll
            for (int i = 0; i < 8; i++) a[i] = fmaf(v[3 * dyi + i], wv, a[i]);
        }
    }
    float* op = out + (size_t)bc * HW + (size_t)(y0 + ty) * WWD + x0 + tx;
#pragma unroll
    for (int i = 0; i < 8; i++) op[i * WWD] = a[i];
}

// ---------------- GN affine coefficients ----------------
__global__ void affine_kernel(const float* __restrict__ kvg, const float* __restrict__ kvb,
                              const float* __restrict__ qg, const float* __restrict__ qb)
{
    int t = threadIdx.x;
    if (t < 512) {
        int b = t >> 7, ch = t & 127, g = ch >> 6;
        double N = 64.0 * HW;
        double mu = g_sum_kv[b * 4 + g * 2] / N;
        double var = g_sum_kv[b * 4 + g * 2 + 1] / N - mu * mu;
        float a = kvg[ch] * (float)(1.0 / sqrt(var + 1e-5));
        g_aff_kv[(b * 128 + ch) * 2] = a;
        g_aff_kv[(b * 128 + ch) * 2 + 1] = kvb[ch] - (float)mu * a;
    }
    if (t < 256) {
        int b = t >> 6, ch = t & 63, g = ch >> 5;
        double N = 32.0 * HW;
        double mu = g_sum_q[b * 4 + g * 2] / N;
        double var = g_sum_q[b * 4 + g * 2 + 1] / N - mu * mu;
        float a = qg[ch] * (float)(1.0 / sqrt(var + 1e-5));
        g_aff_q[(b * 64 + ch) * 2] = a;
        g_aff_q[(b * 64 + ch) * 2 + 1] = qb[ch] - (float)mu * a;
    }
}

// ---------------- gram: G[b,h] = qt @ ktT, plus L2 sums ----------------
__global__ void __launch_bounds__(256) gram_kernel() {
    int b = blockIdx.z, h = blockIdx.y, chunk = blockIdx.x;
    int tid = threadIdx.x;
    __shared__ float sq[16][130], sk[16][130];
    __shared__ float aq[16][2], ak[16][2];
    if (tid < 16) {
        aq[tid][0] = g_aff_q[(b * 64 + h * 16 + tid) * 2];
        aq[tid][1] = g_aff_q[(b * 64 + h * 16 + tid) * 2 + 1];
    } else if (tid < 32) {
        int rr = tid - 16;
        ak[rr][0] = g_aff_kv[(b * 128 + h * 16 + rr) * 2];
        ak[rr][1] = g_aff_kv[(b * 128 + h * 16 + rr) * 2 + 1];
    }
    __syncthreads();
    const int c = tid >> 4, d = tid & 15;
    float gacc = 0.f, qs = 0.f, ks = 0.f;
    const float* qbp = g_q0  + ((size_t)(b * 64  + h * 16)) * HW + chunk * 4096;
    const float* kbp = g_kv0 + ((size_t)(b * 128 + h * 16)) * HW + chunk * 4096;
    for (int t = 0; t < 32; t++) {
#pragma unroll
        for (int l = 0; l < 2; l++) {
            int v = tid + l * 256;
            int row = v >> 5, col4 = v & 31;
            float4 xq = *(const float4*)(qbp + (size_t)row * HW + t * 128 + col4 * 4);
            float4 xk = *(const float4*)(kbp + (size_t)row * HW + t * 128 + col4 * 4);
            float a0 = aq[row][0], b0 = aq[row][1];
            float a1 = ak[row][0], b1 = ak[row][1];
            sq[row][col4 * 4 + 0] = lrelu(fmaf(a0, xq.x, b0));
            sq[row][col4 * 4 + 1] = lrelu(fmaf(a0, xq.y, b0));
            sq[row][col4 * 4 + 2] = lrelu(fmaf(a0, xq.z, b0));
            sq[row][col4 * 4 + 3] = lrelu(fmaf(a0, xq.w, b0));
            sk[row][col4 * 4 + 0] = lrelu(fmaf(a1, xk.x, b1));
            sk[row][col4 * 4 + 1] = lrelu(fmaf(a1, xk.y, b1));
            sk[row][col4 * 4 + 2] = lrelu(fmaf(a1, xk.z, b1));
            sk[row][col4 * 4 + 3] = lrelu(fmaf(a1, xk.w, b1));
        }
        __syncthreads();
#pragma unroll 8
        for (int p = 0; p < 128; p++) {
            float qv = sq[c][p], kv = sk[d][p];
            gacc = fmaf(qv, kv, gacc);
            if (d == 0) qs = fmaf(qv, qv, qs);
            if (c == 0) ks = fmaf(kv, kv, ks);
        }
        __syncthreads();
    }
    atomicAdd(&g_G[((b * 4 + h) * 16 + c) * 16 + d], gacc);
    if (d == 0) atomicAdd(&g_qss[(b * 4 + h) * 16 + c], qs);
    if (c == 0) atomicAdd(&g_kss[(b * 4 + h) * 16 + d], ks);
}

// ---------------- softmax + M = projW @ blockdiag(attn) ----------------
__global__ void attnm_kernel(const float* __restrict__ projW, const float* __restrict__ temp) {
    int b = blockIdx.x, tid = threadIdx.x;
    __shared__ float qn[64], kn[64], attn[4][16][16];
    if (tid < 64) {
        qn[tid] = fmaxf(sqrtf(g_qss[b * 64 + tid]), 1e-12f);
        kn[tid] = fmaxf(sqrtf(g_kss[b * 64 + tid]), 1e-12f);
    }
    __syncthreads();
    if (tid < 64) {
        int h = tid >> 4, c = tid & 15;
        float tv = temp[h];
        float e[16], mx = -1e30f;
        float qi = 1.f / qn[h * 16 + c];
        for (int d = 0; d < 16; d++) {
            e[d] = g_G[((b * 4 + h) * 16 + c) * 16 + d] * tv * qi / kn[h * 16 + d];
            mx = fmaxf(mx, e[d]);
        }
        float sum = 0.f;
        for (int d = 0; d < 16; d++) { e[d] = expf(e[d] - mx); sum += e[d]; }
        float inv = 1.f / sum;
        for (int d = 0; d < 16; d++) attn[h][c][d] = e[d] * inv;
    }
    __syncthreads();
    for (int t = tid; t < 4096; t += 256) {
        int oc = t >> 6, cv = t & 63;
        int h = cv >> 4, j = cv & 15;
        float acc = 0.f;
#pragma unroll
        for (int c = 0; c < 16; c++)
            acc = fmaf(projW[oc * 64 + h * 16 + c], attn[h][c][j], acc);
        g_M[b * 4096 + t] = acc;
    }
}

// ---------------- host launch ----------------
extern "C" void kernel_launch(void* const* d_in, const int* in_sizes, int n_in,
                              void* d_out, int out_size) {
    const float* x       = (const float*)d_in[0];
    const float* y       = (const float*)d_in[1];
    const float* kv_w    = (const float*)d_in[2];
    const float* q_w     = (const float*)d_in[3];
    const float* proj_w  = (const float*)d_in[4];
    const float* kv_c0_w = (const float*)d_in[5];
    const float* kv_c0_b = (const float*)d_in[6];
    const float* kv_cs_w = (const float*)d_in[7];
    const float* kv_cs_b = (const float*)d_in[8];
    const float* kv_c1_w = (const float*)d_in[9];
    const float* kv_c1_b = (const float*)d_in[10];
    const float* kv_gn_g = (const float*)d_in[11];
    const float* kv_gn_b = (const float*)d_in[12];
    const float* q_c0_w  = (const float*)d_in[13];
    const float* q_c0_b  = (const float*)d_in[14];
    const float* q_cs_w  = (const float*)d_in[15];
    const float* q_cs_b  = (const float*)d_in[16];
    const float* q_c1_w  = (const float*)d_in[17];
    const float* q_c1_b  = (const float*)d_in[18];
    const float* q_gn_g  = (const float*)d_in[19];
    const float* q_gn_b  = (const float*)d_in[20];
    const float* temp    = (const float*)d_in[21];
    float* out = (float*)d_out;

    float *kv0, *kv1, *q0, *q1, *affkv, *Mp;
    double *skv, *sq;
    cudaGetSymbolAddress((void**)&kv0, g_kv0);
    cudaGetSymbolAddress((void**)&kv1, g_kv1);
    cudaGetSymbolAddress((void**)&q0, g_q0);
    cudaGetSymbolAddress((void**)&q1, g_q1);
    cudaGetSymbolAddress((void**)&affkv, g_aff_kv);
    cudaGetSymbolAddress((void**)&Mp, g_M);
    cudaGetSymbolAddress((void**)&skv, g_sum_kv);
    cudaGetSymbolAddress((void**)&sq, g_sum_q);

    cudaFuncSetAttribute((const void*)pw_split,
                         cudaFuncAttributeMaxDynamicSharedMemorySize, 128 * 128 * 4);

    zero_kernel<<<1, 256>>>();

    pw_kernel<64, 64, 128, false, false, false><<<dim3(512, 4), 256, 64 * 128 * 4>>>(
        x, (size_t)64 * HW, q_w, 0, nullptr, nullptr, 0, 0, q0, nullptr);
    pw_kernel<64, 128, 128, false, false, false><<<dim3(512, 4), 256, 64 * 128 * 4>>>(
        y, (size_t)64 * HW, kv_w, 0, nullptr, nullptr, 0, 0, kv0, nullptr);

    // merged depthwise: z<256 -> q branch, z>=256 -> kv branch
    dwf_kernel<<<dim3(4, 8, 256 + 512), 256>>>(
        q0, q1, kv0, kv1,
        q_c0_w, q_c0_b, q_cs_w, q_cs_b,
        kv_c0_w, kv_c0_b, kv_cs_w, kv_cs_b);

    pw_kernel<64, 64, 128, true, true, false><<<dim3(512, 4), 256, 64 * 128 * 4>>>(
        q1, (size_t)64 * HW, q_c1_w, 0, q_c1_b, nullptr, 0, 0, q0, sq);
    // kv-c1 COUT-split: z selects oc half; 3 blocks/SM
    pw_split<<<dim3(512, 4, 2), 256, 128 * 128 * 4>>>(
        kv1, kv_c1_w, kv_c1_b, kv0, skv);

    affine_kernel<<<1, 512>>>(kv_gn_g, kv_gn_b, q_gn_g, q_gn_b);

    gram_kernel<<<dim3(16, 4, BB), 256>>>();

    attnm_kernel<<<BB, 256>>>(proj_w, temp);

    pw_kernel<64, 64, 128, false, false, true><<<dim3(512, 4), 256, 64 * 128 * 4>>>(
        kv0 + (size_t)64 * HW, (size_t)128 * HW, Mp, 4096, nullptr,
        affkv, 64, 128, out, nullptr);
}

// round 17
// speedup vs baseline: 1.0789x; 1.0789x over previous
// ============================================================================
// R17 submission.
//
// Post-mortem R16: COUT-split kv-c1 REGRESSED (810 -> 864). The doubled input
// staging (each half re-stages the full 64KB tile) cost more than the extra
// occupancy bought — same lesson as R14 from the other axis. kv-c1 splitting
// in ANY axis is now closed; the R10/R15 monolithic pw shape is the proven
// local optimum for the big GEMM.
//
// R17 = R15 exact (proven 810.2) + ONE low-risk occupancy knob on the three
// SMALL pw instances (CIN=64, COUT=64: q-proj, q-c1, final-VAFF):
//   Add a MinBlocks template parameter -> __launch_bounds__(256, MINB).
//   These instances use 32KB smem (7 blocks/SM smem-wise) but ~90+ regs
//   (2 blocks/SM RF-wise). MINB=3 caps regs at 85: acc(32 u64)=32 + wq(4
//   float4)=16 + xv(4 u64)=8 + indexing fits without meaningful spill.
//   2 -> 3 blocks/SM on ~190us of kernels; the occ->issue relation that held
//   for dwf (R9/R11) predicts ~15-20% on those kernels.
//   kv-proj (COUT=128) and kv-c1 keep MINB=2 (higher reg need; default
//   measured best).
//
// Prediction: 810 -> ~785-795us, rel_err ~6.6e-7. Worst case neutral (if
// those instances already fit 3 blocks). If neutral, pw direction is
// exhausted and next round pivots to gram/tail or stream-overlap.
// ============================================================================
#include <cuda_runtime.h>
#include <cstdint>
#include <cstddef>
#include <math.h>

#define HW   65536
#define HH   256
#define WWD  256
#define BB   4

// ---------------- scratch (static device globals; no allocation) ----------------
__device__ float  g_kv0[(size_t)BB * 128 * HW];
__device__ float  g_kv1[(size_t)BB * 128 * HW];
__device__ float  g_q0 [(size_t)BB * 64  * HW];
__device__ float  g_q1 [(size_t)BB * 64  * HW];
__device__ double g_sum_kv[BB * 4];
__device__ double g_sum_q [BB * 4];
__device__ float  g_aff_kv[BB * 128 * 2];
__device__ float  g_aff_q [BB * 64  * 2];
__device__ float  g_G  [BB * 4 * 256];
__device__ float  g_qss[BB * 4 * 16];
__device__ float  g_kss[BB * 4 * 16];
__device__ float  g_M  [BB * 64 * 64];

// ---------------- helpers ----------------
__device__ __forceinline__ unsigned long long pk2(float a, float b) {
    unsigned long long r;
    asm("mov.b64 %0, {%1,%2};" : "=l"(r) : "f"(a), "f"(b));
    return r;
}
__device__ __forceinline__ unsigned long long fma2(unsigned long long a, unsigned long long b,
                                                   unsigned long long c) {
    unsigned long long d;
    asm("fma.rn.f32x2 %0, %1, %2, %3;" : "=l"(d) : "l"(a), "l"(b), "l"(c));
    return d;
}
__device__ __forceinline__ float2 up2(unsigned long long v) {
    float2 r;
    asm("mov.b64 {%0,%1}, %2;" : "=f"(r.x), "=f"(r.y) : "l"(v));
    return r;
}
__device__ __forceinline__ float lrelu(float x) { return x > 0.f ? x : 0.2f * x; }

// ---------------- zero small reduction buffers ----------------
__global__ void zero_kernel() {
    int t = threadIdx.x;
    if (t < 16) { g_sum_kv[t] = 0.0; g_sum_q[t] = 0.0; }
    for (int i = t; i < 4096; i += 256) g_G[i] = 0.f;
    g_qss[t] = 0.f; g_kss[t] = 0.f;
}

// ---------------- pointwise 1x1 conv (tall GEMM), packed f32x2 ------------------
// R10 body; MINB = min-blocks-per-SM occupancy hint (template knob).
template <int CIN, int COUT, int PIX, bool BIAS, bool STATS, bool VAFF, int MINB>
__global__ void __launch_bounds__(256, MINB) pw_kernel(
    const float* __restrict__ in, size_t inBStride,
    const float* __restrict__ w, size_t wBStride,
    const float* __restrict__ bias,
    const float* __restrict__ aff, int affCOff, int affCStride,
    float* __restrict__ out, double* __restrict__ stats)
{
    extern __shared__ float sm[];          // CIN * PIX floats
    __shared__ float red[256][4];
    const int tid = threadIdx.x;
    const int b = blockIdx.y;
    const int pix0 = blockIdx.x * PIX;
    const float* ib = in + (size_t)b * inBStride + pix0;
    const float* wb = w + (size_t)b * wBStride;

    constexpr int P4 = PIX / 4;
#pragma unroll
    for (int l = 0; l < CIN * PIX / 1024; l++) {
        int idx = tid + l * 256;
        int c = idx / P4, p4 = idx % P4;
        float4 v = *(const float4*)(ib + (size_t)c * HW + p4 * 4);
        if (VAFF) {
            const float* ap = aff + ((size_t)b * affCStride + affCOff + c) * 2;
            float aa = ap[0], bc = ap[1];
            v.x = lrelu(fmaf(aa, v.x, bc));
            v.y = lrelu(fmaf(aa, v.y, bc));
            v.z = lrelu(fmaf(aa, v.z, bc));
            v.w = lrelu(fmaf(aa, v.w, bc));
        }
        *(float4*)(sm + c * PIX + p4 * 4) = v;
    }
    __syncthreads();

    constexpr int JM = COUT / 16;
    constexpr int NI = PIX / 32;
    unsigned long long acc[JM][NI];
#pragma unroll
    for (int j = 0; j < JM; j++)
#pragma unroll
        for (int i = 0; i < NI; i++) acc[j][i] = 0ull;

    const int r = tid >> 4, cp = tid & 15;
    const unsigned long long* s2 = (const unsigned long long*)sm;

    for (int k0 = 0; k0 < CIN; k0 += 4) {
        float4 wq[JM];
#pragma unroll
        for (int j = 0; j < JM; j++)
            wq[j] = *(const float4*)(wb + (r + 16 * j) * CIN + k0);
#pragma unroll
        for (int kk = 0; kk < 4; kk++) {
            int k = k0 + kk;
            unsigned long long xv[NI];
#pragma unroll
            for (int i = 0; i < NI; i++) xv[i] = s2[k * (PIX / 2) + cp + 16 * i];
#pragma unroll
            for (int j = 0; j < JM; j++) {
                float wv = ((const float*)&wq[j])[kk];
                unsigned long long wp = pk2(wv, wv);
#pragma unroll
                for (int i = 0; i < NI; i++) acc[j][i] = fma2(xv[i], wp, acc[j][i]);
            }
        }
    }

    float sumg[2] = {0.f, 0.f}, ssqg[2] = {0.f, 0.f};
#pragma unroll
    for (int j = 0; j < JM; j++) {
        int oc = r + 16 * j;
        float bs = BIAS ? bias[oc] : 0.f;
        float* op = out + ((size_t)b * COUT + oc) * HW + pix0;
#pragma unroll
        for (int i = 0; i < NI; i++) {
            float2 v = up2(acc[j][i]);
            v.x += bs; v.y += bs;
            *(float2*)(op + 2 * (cp + 16 * i)) = v;
            if (STATS) {
                int g = (j >= JM / 2) ? 1 : 0;
                sumg[g] += v.x + v.y;
                ssqg[g] += v.x * v.x + v.y * v.y;
            }
        }
    }

    if (STATS) {
        red[tid][0] = sumg[0]; red[tid][1] = ssqg[0];
        red[tid][2] = sumg[1]; red[tid][3] = ssqg[1];
        __syncthreads();
        for (int s = 128; s > 0; s >>= 1) {
            if (tid < s) {
#pragma unroll
                for (int m = 0; m < 4; m++) red[tid][m] += red[tid + s][m];
            }
            __syncthreads();
        }
        if (tid == 0) {
            atomicAdd(&stats[b * 4 + 0], (double)red[0][0]);
            atomicAdd(&stats[b * 4 + 1], (double)red[0][1]);
            atomicAdd(&stats[b * 4 + 2], (double)red[0][2]);
            atomicAdd(&stats[b * 4 + 3], (double)red[0][3]);
        }
    }
}

// ---------------- fused depthwise, MERGED q+kv launch (R15-exact) --------------
__global__ void __launch_bounds__(256, 6) dwf_kernel(
    const float* __restrict__ qin,  float* __restrict__ qout,
    const float* __restrict__ kin,  float* __restrict__ kout,
    const float* __restrict__ qw5, const float* __restrict__ qb5,
    const float* __restrict__ qw3, const float* __restrict__ qb3,
    const float* __restrict__ kw5, const float* __restrict__ kb5,
    const float* __restrict__ kw3, const float* __restrict__ kb3)
{
    __shared__ float s[44][76];
    __shared__ float m[38][72];
    __shared__ float wts[36];
    const int tid = threadIdx.x;
    const bool isq = (blockIdx.z < 256);
    const int bc = isq ? blockIdx.z : (blockIdx.z - 256);
    const int C = isq ? 64 : 128;
    const int c = bc % C;
    const float* in = (isq ? qin : kin);
    float* out = (isq ? qout : kout);
    const float* w5 = isq ? qw5 : kw5;
    const float* b5 = isq ? qb5 : kb5;
    const float* w3 = isq ? qw3 : kw3;
    const float* b3 = isq ? qb3 : kb3;
    const int x0 = blockIdx.x * 64, y0 = blockIdx.y * 32;

    if (tid < 25) wts[tid] = w5[c * 25 + tid];
    else if (tid == 25) wts[25] = b5[c];
    else if (tid < 35) wts[tid] = w3[c * 9 + (tid - 26)];
    else if (tid == 35) wts[35] = b3[c];

    const float* ip = in + (size_t)bc * HW;
    for (int idx = tid; idx < 42 * 74; idx += 256) {
        int row = idx / 74, col = idx % 74;
        int gy = y0 + row - 5, gx = x0 + col - 5;
        float v = 0.f;
        if (gy >= 0 && gy < HH && gx >= 0 && gx < WWD) v = ip[gy * WWD + gx];
        s[row][col] = v;
    }
    __syncthreads();

    for (int t = tid; t < 350; t += 256) {
        int ss = t / 70, j = t % 70;
        int r0 = ss * 8;
        int nr = 38 - r0; if (nr > 8) nr = 8;
        int gx = x0 - 3 + j;
        bool xin = (gx >= 0 && gx < WWD);
        float acc[8];
#pragma unroll
        for (int i = 0; i < 8; i++) acc[i] = wts[25];
#pragma unroll
        for (int dx = 0; dx < 5; dx++) {
            float v[12];
#pragma unroll
            for (int rr = 0; rr < 12; rr++) v[rr] = s[r0 + rr][j + dx];
#pragma unroll
            for (int dy = 0; dy < 5; dy++) {
                float wv = wts[dy * 5 + dx];
#pragma unroll
                for (int i = 0; i < 8; i++) acc[i] = fmaf(v[dy + i], wv, acc[i]);
            }
        }
#pragma unroll
        for (int i = 0; i < 8; i++) {
            if (i < nr) {
                int gy = y0 - 3 + r0 + i;
                bool in_img = xin && (gy >= 0) && (gy < HH);
                m[r0 + i][j] = in_img ? acc[i] : 0.f;
            }
        }
    }
    __syncthreads();

    const int tx = tid & 63, ty = (tid >> 6) << 3;
    float bs = wts[35];
    float a[8];
#pragma unroll
    for (int i = 0; i < 8; i++) a[i] = bs;
#pragma unroll
    for (int dxi = 0; dxi < 3; dxi++) {
        int colx = tx + 3 * dxi;
        float v[14];
#pragma unroll
        for (int rr = 0; rr < 14; rr++) v[rr] = m[ty + rr][colx];
#pragma unroll
        for (int dyi = 0; dyi < 3; dyi++) {
            float wv = wts[26 + dyi * 3 + dxi];
#pragma unroll
            for (int i = 0; i < 8; i++) a[i] = fmaf(v[3 * dyi + i], wv, a[i]);
        }
    }
    float* op = out + (size_t)bc * HW + (size_t)(y0 + ty) * WWD + x0 + tx;
#pragma unroll
    for (int i = 0; i < 8; i++) op[i * WWD] = a[i];
}

// ---------------- GN affine coefficients ----------------
__global__ void affine_kernel(const float* __restrict__ kvg, const float* __restrict__ kvb,
                              const float* __restrict__ qg, const float* __restrict__ qb)
{
    int t = threadIdx.x;
    if (t < 512) {
        int b = t >> 7, ch = t & 127, g = ch >> 6;
        double N = 64.0 * HW;
        double mu = g_sum_kv[b * 4 + g * 2] / N;
        double var = g_sum_kv[b * 4 + g * 2 + 1] / N - mu * mu;
        float a = kvg[ch] * (float)(1.0 / sqrt(var + 1e-5));
        g_aff_kv[(b * 128 + ch) * 2] = a;
        g_aff_kv[(b * 128 + ch) * 2 + 1] = kvb[ch] - (float)mu * a;
    }
    if (t < 256) {
        int b = t >> 6, ch = t & 63, g = ch >> 5;
        double N = 32.0 * HW;
        double mu = g_sum_q[b * 4 + g * 2] / N;
        double var = g_sum_q[b * 4 + g * 2 + 1] / N - mu * mu;
        float a = qg[ch] * (float)(1.0 / sqrt(var + 1e-5));
        g_aff_q[(b * 64 + ch) * 2] = a;
        g_aff_q[(b * 64 + ch) * 2 + 1] = qb[ch] - (float)mu * a;
    }
}

// ---------------- gram: G[b,h] = qt @ ktT, plus L2 sums ----------------
__global__ void __launch_bounds__(256) gram_kernel() {
    int b = blockIdx.z, h = blockIdx.y, chunk = blockIdx.x;
    int tid = threadIdx.x;
    __shared__ float sq[16][130], sk[16][130];
    __shared__ float aq[16][2], ak[16][2];
    if (tid < 16) {
        aq[tid][0] = g_aff_q[(b * 64 + h * 16 + tid) * 2];
        aq[tid][1] = g_aff_q[(b * 64 + h * 16 + tid) * 2 + 1];
    } else if (tid < 32) {
        int rr = tid - 16;
        ak[rr][0] = g_aff_kv[(b * 128 + h * 16 + rr) * 2];
        ak[rr][1] = g_aff_kv[(b * 128 + h * 16 + rr) * 2 + 1];
    }
    __syncthreads();
    const int c = tid >> 4, d = tid & 15;
    float gacc = 0.f, qs = 0.f, ks = 0.f;
    const float* qbp = g_q0  + ((size_t)(b * 64  + h * 16)) * HW + chunk * 4096;
    const float* kbp = g_kv0 + ((size_t)(b * 128 + h * 16)) * HW + chunk * 4096;
    for (int t = 0; t < 32; t++) {
#pragma unroll
        for (int l = 0; l < 2; l++) {
            int v = tid + l * 256;
            int row = v >> 5, col4 = v & 31;
            float4 xq = *(const float4*)(qbp + (size_t)row * HW + t * 128 + col4 * 4);
            float4 xk = *(const float4*)(kbp + (size_t)row * HW + t * 128 + col4 * 4);
            float a0 = aq[row][0], b0 = aq[row][1];
            float a1 = ak[row][0], b1 = ak[row][1];
            sq[row][col4 * 4 + 0] = lrelu(fmaf(a0, xq.x, b0));
            sq[row][col4 * 4 + 1] = lrelu(fmaf(a0, xq.y, b0));
            sq[row][col4 * 4 + 2] = lrelu(fmaf(a0, xq.z, b0));
            sq[row][col4 * 4 + 3] = lrelu(fmaf(a0, xq.w, b0));
            sk[row][col4 * 4 + 0] = lrelu(fmaf(a1, xk.x, b1));
            sk[row][col4 * 4 + 1] = lrelu(fmaf(a1, xk.y, b1));
            sk[row][col4 * 4 + 2] = lrelu(fmaf(a1, xk.z, b1));
            sk[row][col4 * 4 + 3] = lrelu(fmaf(a1, xk.w, b1));
        }
        __syncthreads();
#pragma unroll 8
        for (int p = 0; p < 128; p++) {
            float qv = sq[c][p], kv = sk[d][p];
            gacc = fmaf(qv, kv, gacc);
            if (d == 0) qs = fmaf(qv, qv, qs);
            if (c == 0) ks = fmaf(kv, kv, ks);
        }
        __syncthreads();
    }
    atomicAdd(&g_G[((b * 4 + h) * 16 + c) * 16 + d], gacc);
    if (d == 0) atomicAdd(&g_qss[(b * 4 + h) * 16 + c], qs);
    if (c == 0) atomicAdd(&g_kss[(b * 4 + h) * 16 + d], ks);
}

// ---------------- softmax + M = projW @ blockdiag(attn) ----------------
__global__ void attnm_kernel(const float* __restrict__ projW, const float* __restrict__ temp) {
    int b = blockIdx.x, tid = threadIdx.x;
    __shared__ float qn[64], kn[64], attn[4][16][16];
    if (tid < 64) {
        qn[tid] = fmaxf(sqrtf(g_qss[b * 64 + tid]), 1e-12f);
        kn[tid] = fmaxf(sqrtf(g_kss[b * 64 + tid]), 1e-12f);
    }
    __syncthreads();
    if (tid < 64) {
        int h = tid >> 4, c = tid & 15;
        float tv = temp[h];
        float e[16], mx = -1e30f;
        float qi = 1.f / qn[h * 16 + c];
        for (int d = 0; d < 16; d++) {
            e[d] = g_G[((b * 4 + h) * 16 + c) * 16 + d] * tv * qi / kn[h * 16 + d];
            mx = fmaxf(mx, e[d]);
        }
        float sum = 0.f;
        for (int d = 0; d < 16; d++) { e[d] = expf(e[d] - mx); sum += e[d]; }
        float inv = 1.f / sum;
        for (int d = 0; d < 16; d++) attn[h][c][d] = e[d] * inv;
    }
    __syncthreads();
    for (int t = tid; t < 4096; t += 256) {
        int oc = t >> 6, cv = t & 63;
        int h = cv >> 4, j = cv & 15;
        float acc = 0.f;
#pragma unroll
        for (int c = 0; c < 16; c++)
            acc = fmaf(projW[oc * 64 + h * 16 + c], attn[h][c][j], acc);
        g_M[b * 4096 + t] = acc;
    }
}

// ---------------- host launch ----------------
extern "C" void kernel_launch(void* const* d_in, const int* in_sizes, int n_in,
                              void* d_out, int out_size) {
    const float* x       = (const float*)d_in[0];
    const float* y       = (const float*)d_in[1];
    const float* kv_w    = (const float*)d_in[2];
    const float* q_w     = (const float*)d_in[3];
    const float* proj_w  = (const float*)d_in[4];
    const float* kv_c0_w = (const float*)d_in[5];
    const float* kv_c0_b = (const float*)d_in[6];
    const float* kv_cs_w = (const float*)d_in[7];
    const float* kv_cs_b = (const float*)d_in[8];
    const float* kv_c1_w = (const float*)d_in[9];
    const float* kv_c1_b = (const float*)d_in[10];
    const float* kv_gn_g = (const float*)d_in[11];
    const float* kv_gn_b = (const float*)d_in[12];
    const float* q_c0_w  = (const float*)d_in[13];
    const float* q_c0_b  = (const float*)d_in[14];
    const float* q_cs_w  = (const float*)d_in[15];
    const float* q_cs_b  = (const float*)d_in[16];
    const float* q_c1_w  = (const float*)d_in[17];
    const float* q_c1_b  = (const float*)d_in[18];
    const float* q_gn_g  = (const float*)d_in[19];
    const float* q_gn_b  = (const float*)d_in[20];
    const float* temp    = (const float*)d_in[21];
    float* out = (float*)d_out;

    float *kv0, *kv1, *q0, *q1, *affkv, *Mp;
    double *skv, *sq;
    cudaGetSymbolAddress((void**)&kv0, g_kv0);
    cudaGetSymbolAddress((void**)&kv1, g_kv1);
    cudaGetSymbolAddress((void**)&q0, g_q0);
    cudaGetSymbolAddress((void**)&q1, g_q1);
    cudaGetSymbolAddress((void**)&affkv, g_aff_kv);
    cudaGetSymbolAddress((void**)&Mp, g_M);
    cudaGetSymbolAddress((void**)&skv, g_sum_kv);
    cudaGetSymbolAddress((void**)&sq, g_sum_q);

    cudaFuncSetAttribute((const void*)pw_kernel<128, 128, 128, true, true, false, 2>,
                         cudaFuncAttributeMaxDynamicSharedMemorySize, 128 * 128 * 4);

    zero_kernel<<<1, 256>>>();

    // small pw instances get MINB=3 (occupancy 2 -> 3 blocks/SM)
    pw_kernel<64, 64, 128, false, false, false, 3><<<dim3(512, 4), 256, 64 * 128 * 4>>>(
        x, (size_t)64 * HW, q_w, 0, nullptr, nullptr, 0, 0, q0, nullptr);
    pw_kernel<64, 128, 128, false, false, false, 2><<<dim3(512, 4), 256, 64 * 128 * 4>>>(
        y, (size_t)64 * HW, kv_w, 0, nullptr, nullptr, 0, 0, kv0, nullptr);

    // merged depthwise: z<256 -> q branch, z>=256 -> kv branch
    dwf_kernel<<<dim3(4, 8, 256 + 512), 256>>>(
        q0, q1, kv0, kv1,
        q_c0_w, q_c0_b, q_cs_w, q_cs_b,
        kv_c0_w, kv_c0_b, kv_cs_w, kv_cs_b);

    pw_kernel<64, 64, 128, true, true, false, 3><<<dim3(512, 4), 256, 64 * 128 * 4>>>(
        q1, (size_t)64 * HW, q_c1_w, 0, q_c1_b, nullptr, 0, 0, q0, sq);
    pw_kernel<128, 128, 128, true, true, false, 2><<<dim3(512, 4), 256, 128 * 128 * 4>>>(
        kv1, (size_t)128 * HW, kv_c1_w, 0, kv_c1_b, nullptr, 0, 0, kv0, skv);

    affine_kernel<<<1, 512>>>(kv_gn_g, kv_gn_b, q_gn_g, q_gn_b);

    gram_kernel<<<dim3(16, 4, BB), 256>>>();

    attnm_kernel<<<BB, 256>>>(proj_w, temp);

    pw_kernel<64, 64, 128, false, false, true, 3><<<dim3(512, 4), 256, 64 * 128 * 4>>>(
        kv0 + (size_t)64 * HW, (size_t)128 * HW, Mp, 4096, nullptr,
        affkv, 64, 128, out, nullptr);
}